// round 10
// baseline (speedup 1.0000x reference)
#include <cuda_runtime.h>
#include <cuda_fp16.h>
#include <stdint.h>

// bg: (1, 4, 32, 32, 32, 16) float32  -> d_in[0]
// gm: (1, 1, 128, 128, 128) float32   -> d_in[1]
// out: (1, 4, 128, 128, 128) float32

#define UP 16
#define G  128
#define NVOX (G * G * G)                 // 2,097,152
#define BG_SPATIAL (32 * 32 * 32 * 16)   // 524,288

// Delta-paired fp16 grid: entry (x,y,z,t) = 16B {v4[t], v4[t+1]-v4[t]}
// (t+1 clamped to 15 -> delta 0). 8.4 MB static device scratch.
__device__ uint4 g_bgP[BG_SPATIAL];

// ---------------------------------------------------------------------------
// Kernel 1: transpose (c,x,y,z,t) -> delta-paired channel-last fp16.
// ---------------------------------------------------------------------------
__global__ void bgT_pair_kernel(const float* __restrict__ bg) {
    int idx = blockIdx.x * blockDim.x + threadIdx.x;
    if (idx >= BG_SPATIAL) return;
    float a = __ldg(&bg[0 * BG_SPATIAL + idx]);
    float b = __ldg(&bg[1 * BG_SPATIAL + idx]);
    float c = __ldg(&bg[2 * BG_SPATIAL + idx]);
    float d = __ldg(&bg[3 * BG_SPATIAL + idx]);
    __half2 lo = __floats2half2_rn(a, b);
    __half2 hi = __floats2half2_rn(c, d);
    uint32_t ulo = *reinterpret_cast<uint32_t*>(&lo);
    uint32_t uhi = *reinterpret_cast<uint32_t*>(&hi);
    // neighbor (t+1) within 16-lane segment; lane 15 keeps own value (clamp)
    uint32_t nlo = __shfl_down_sync(0xffffffffu, ulo, 1, 16);
    uint32_t nhi = __shfl_down_sync(0xffffffffu, uhi, 1, 16);
    __half2 dlo = __hsub2(*reinterpret_cast<__half2*>(&nlo), lo);
    __half2 dhi = __hsub2(*reinterpret_cast<__half2*>(&nhi), hi);
    uint4 e;
    e.x = ulo; e.y = uhi;
    e.z = *reinterpret_cast<uint32_t*>(&dlo);
    e.w = *reinterpret_cast<uint32_t*>(&dhi);
    g_bgP[idx] = e;
}

// ---------------------------------------------------------------------------
// Kernel 2: slice with x-prelerped smem tile.
// Tile = 4(gh) x 16(gw) x 16(gd) = 1024 voxels, 512 threads, 2 vox/thread.
// smem tile: [xr(4)][cy(6)][cz(6)][t(16)] entries of 16B, each already
// x-interpolated for its gh row (fp16 lerp at fill). Gather = 4 corners
// (y0/y1 x z0/z1), each 1 IADD + 1 LDS.128 + fp16 t-lerp + fp32 accum.
// ---------------------------------------------------------------------------
#define CY 6
#define CZ 6
#define NENT (4 * CY * CZ * 16)      // 2304 entries = 36864 B
#define ZS 16                        // slot stride per z-cell
#define YS (CZ * 16)                 // 96
#define XS (CY * CZ * 16)            // 576

__global__ __launch_bounds__(512)
void bgrid_slice_kernel(const float* __restrict__ gm, float* __restrict__ out) {
    __shared__ uint4    sgrid[NENT];      // 36864 B
    __shared__ int      sOffY[16], sDY[16];
    __shared__ int      sOffZ[16], sDZ[16];
    __shared__ float    sFy[16], sFz[16];
    __shared__ int      sX0[4], sX1[4];
    __shared__ uint32_t sFxh[4];          // half2(fx,fx)

    int tid = threadIdx.x;
    int bd = blockIdx.x & 7;            // 8 gd tiles of 16
    int bw = (blockIdx.x >> 3) & 7;     // 8 gw tiles of 16
    int bh = blockIdx.x >> 6;           // 32 gh tiles of 4

    int gh0 = bh << 2, gw0 = bw << 4, gd0 = bd << 4;

    const float s = 31.0f / 127.0f;
    int by0 = (int)floorf((float)gw0 * s);
    int bz0 = (int)floorf((float)gd0 * s);

    // ---- axis LUTs (36 threads) ----
    if (tid < 36) {
        if (tid < 16) {                 // z axis
            float v = fminf(fmaxf((float)(gd0 + tid) * s, 0.0f), 31.0f);
            int i0 = (int)floorf(v);
            int i1 = min(i0 + 1, 31);
            sOffZ[tid] = (i0 - bz0) * ZS;
            sDZ[tid]   = (i1 - i0) * ZS;
            sFz[tid]   = v - (float)i0;
        } else if (tid < 32) {          // y axis
            int l = tid - 16;
            float v = fminf(fmaxf((float)(gw0 + l) * s, 0.0f), 31.0f);
            int i0 = (int)floorf(v);
            int i1 = min(i0 + 1, 31);
            sOffY[l] = (i0 - by0) * YS;
            sDY[l]   = (i1 - i0) * YS;
            sFy[l]   = v - (float)i0;
        } else {                        // x rows
            int xr = tid - 32;
            float v = fminf(fmaxf((float)(gh0 + xr) * s, 0.0f), 31.0f);
            int i0 = (int)floorf(v);
            sX0[xr] = i0;
            sX1[xr] = min(i0 + 1, 31);
            float fx = v - (float)i0;
            __half2 h2 = __half2half2(__float2half_rn(fx));
            sFxh[xr] = *reinterpret_cast<uint32_t*>(&h2);
        }
    }
    __syncthreads();

    // ---- fill: 2304 entries, x-lerp in fp16 ----
    for (int e = tid; e < NENT; e += 512) {
        int t    = e & 15;
        int cell = e >> 4;              // xr*36 + cy*6 + cz
        int cz   = cell % CZ;
        int cxy  = cell / CZ;
        int cy   = cxy % CY;
        int xr   = cxy / CY;
        int y = min(by0 + cy, 31);
        int z = min(bz0 + cz, 31);
        int base = (y * 32 + z) * 16 + t;
        uint4 e0 = g_bgP[sX0[xr] * (32 * 32 * 16) + base];
        uint4 e1 = g_bgP[sX1[xr] * (32 * 32 * 16) + base];
        uint32_t fxu = sFxh[xr];
        __half2 fx2 = *reinterpret_cast<__half2*>(&fxu);
        uint4 r;
        {
            __half2 a = *reinterpret_cast<__half2*>(&e0.x);
            __half2 b = *reinterpret_cast<__half2*>(&e1.x);
            __half2 m = __hfma2(fx2, __hsub2(b, a), a);
            r.x = *reinterpret_cast<uint32_t*>(&m);
        }
        {
            __half2 a = *reinterpret_cast<__half2*>(&e0.y);
            __half2 b = *reinterpret_cast<__half2*>(&e1.y);
            __half2 m = __hfma2(fx2, __hsub2(b, a), a);
            r.y = *reinterpret_cast<uint32_t*>(&m);
        }
        {
            __half2 a = *reinterpret_cast<__half2*>(&e0.z);
            __half2 b = *reinterpret_cast<__half2*>(&e1.z);
            __half2 m = __hfma2(fx2, __hsub2(b, a), a);
            r.z = *reinterpret_cast<uint32_t*>(&m);
        }
        {
            __half2 a = *reinterpret_cast<__half2*>(&e0.w);
            __half2 b = *reinterpret_cast<__half2*>(&e1.w);
            __half2 m = __hfma2(fx2, __hsub2(b, a), a);
            r.w = *reinterpret_cast<uint32_t*>(&m);
        }
        sgrid[e] = r;   // slot layout == fill order
    }
    __syncthreads();

    // ---- gather: 2 voxels/thread (xr = xrb, xrb+2) ----
    int ld  = tid & 15;
    int lw  = (tid >> 4) & 15;
    int xrb = tid >> 8;               // 0..1

    int offZ = sOffZ[ld], dZ = sDZ[ld]; float fz = sFz[ld];
    int offY = sOffY[lw], dY = sDY[lw]; float fy = sFy[lw];
    float wz0 = 1.0f - fz, wy0 = 1.0f - fy;
    float w00 = wy0 * wz0, w01 = wy0 * fz, w10 = fy * wz0, w11 = fy * fz;

    int gd = gd0 + ld, gw = gw0 + lw;
    int idx_base = (gw << 7) | gd;

    int   vidx[2];
    float gv[2];
#pragma unroll
    for (int vv = 0; vv < 2; vv++) {
        int xr = xrb + (vv << 1);
        vidx[vv] = ((gh0 + xr) << 14) | idx_base;
        gv[vv] = __ldg(&gm[vidx[vv]]);
    }

#pragma unroll
    for (int vv = 0; vv < 2; vv++) {
        int xr = xrb + (vv << 1);

        float t = fminf(fmaxf(gv[vv] * 15.0f, 0.0f), 15.0f);
        int t0 = (int)floorf(t);
        float ft = t - (float)t0;
        __half2 fth2 = __half2half2(__float2half_rn(ft));

        int b = xr * XS + offY + offZ + t0;
        int c0 = b, c1 = b + dZ, c2 = b + dY, c3 = b + dY + dZ;

        float ax = 0.0f, ay = 0.0f, az = 0.0f, aw = 0.0f;

        const int   cofs[4] = { c0, c1, c2, c3 };
        const float wgts[4] = { w00, w01, w10, w11 };
#pragma unroll
        for (int k = 0; k < 4; k++) {
            uint4 e = sgrid[cofs[k]];
            __half2 v0lo = *reinterpret_cast<__half2*>(&e.x);
            __half2 v0hi = *reinterpret_cast<__half2*>(&e.y);
            __half2 dlo  = *reinterpret_cast<__half2*>(&e.z);
            __half2 dhi  = *reinterpret_cast<__half2*>(&e.w);
            __half2 rlo = __hfma2(fth2, dlo, v0lo);
            __half2 rhi = __hfma2(fth2, dhi, v0hi);
            float2 flo = __half22float2(rlo);
            float2 fhi = __half22float2(rhi);
            float w = wgts[k];
            ax += w * flo.x;
            ay += w * flo.y;
            az += w * fhi.x;
            aw += w * fhi.y;
        }

        out[vidx[vv]]            = ax;
        out[vidx[vv] + NVOX]     = ay;
        out[vidx[vv] + 2 * NVOX] = az;
        out[vidx[vv] + 3 * NVOX] = aw;
    }
}

extern "C" void kernel_launch(void* const* d_in, const int* in_sizes, int n_in,
                              void* d_out, int out_size) {
    const float* bg = (const float*)d_in[0];
    const float* gm = (const float*)d_in[1];
    float* out = (float*)d_out;

    (void)in_sizes; (void)n_in; (void)out_size;

    bgT_pair_kernel<<<(BG_SPATIAL + 255) / 256, 256>>>(bg);
    bgrid_slice_kernel<<<2048, 512>>>(gm, out);
}

// round 11
// speedup vs baseline: 1.0502x; 1.0502x over previous
#include <cuda_runtime.h>
#include <cuda_fp16.h>
#include <stdint.h>

// bg: (1, 4, 32, 32, 32, 16) float32  -> d_in[0]
// gm: (1, 1, 128, 128, 128) float32   -> d_in[1]
// out: (1, 4, 128, 128, 128) float32

#define UP 16
#define G  128
#define NVOX (G * G * G)                 // 2,097,152
#define BG_SPATIAL (32 * 32 * 32 * 16)   // 524,288

// Delta-paired fp16 grid: entry (x,y,z,t) = 16B {v4[t], v4[t+1]-v4[t]}
// (t+1 clamped to 15 -> delta 0). 8.4 MB static device scratch.
__device__ uint4 g_bgP[BG_SPATIAL];

// ---------------------------------------------------------------------------
// Kernel 1: transpose (c,x,y,z,t) -> delta-paired channel-last fp16.
// ---------------------------------------------------------------------------
__global__ void bgT_pair_kernel(const float* __restrict__ bg) {
    int idx = blockIdx.x * blockDim.x + threadIdx.x;
    if (idx >= BG_SPATIAL) return;
    float a = __ldg(&bg[0 * BG_SPATIAL + idx]);
    float b = __ldg(&bg[1 * BG_SPATIAL + idx]);
    float c = __ldg(&bg[2 * BG_SPATIAL + idx]);
    float d = __ldg(&bg[3 * BG_SPATIAL + idx]);
    __half2 lo = __floats2half2_rn(a, b);
    __half2 hi = __floats2half2_rn(c, d);
    uint32_t ulo = *reinterpret_cast<uint32_t*>(&lo);
    uint32_t uhi = *reinterpret_cast<uint32_t*>(&hi);
    // neighbor (t+1) within 16-lane segment; lane 15 keeps own value (clamp)
    uint32_t nlo = __shfl_down_sync(0xffffffffu, ulo, 1, 16);
    uint32_t nhi = __shfl_down_sync(0xffffffffu, uhi, 1, 16);
    __half2 dlo = __hsub2(*reinterpret_cast<__half2*>(&nlo), lo);
    __half2 dhi = __hsub2(*reinterpret_cast<__half2*>(&nhi), hi);
    uint4 e;
    e.x = ulo; e.y = uhi;
    e.z = *reinterpret_cast<uint32_t*>(&dlo);
    e.w = *reinterpret_cast<uint32_t*>(&dhi);
    g_bgP[idx] = e;
}

// ---------------------------------------------------------------------------
// Kernel 2: slice with x-prelerped smem tile.
// Tile = 4(gh) x 16(gw) x 16(gd) = 1024 voxels, 256 threads, 4 vox/thread:
// each thread owns all 4 gh rows of one (gw,gd) column, so the y/z offsets
// and the 4 yz-corner weights are computed once per 4 voxels.
// smem tile: [xr(4)][cy(6)][cz(6)][t(16)] 16B entries, x-prelerped at fill.
// Gather = 4 corners x 1 LDS.128 + fp16 t-lerp + fp32 accum, per voxel.
// ---------------------------------------------------------------------------
#define CY 6
#define CZ 6
#define NENT (4 * CY * CZ * 16)      // 2304 entries = 36864 B
#define ZS 16                        // slot stride per z-cell
#define YS (CZ * 16)                 // 96
#define XS (CY * CZ * 16)            // 576

__global__ __launch_bounds__(256)
void bgrid_slice_kernel(const float* __restrict__ gm, float* __restrict__ out) {
    __shared__ uint4    sgrid[NENT];      // 36864 B
    __shared__ int      sOffY[16], sDY[16];
    __shared__ int      sOffZ[16], sDZ[16];
    __shared__ float    sFy[16], sFz[16];
    __shared__ int      sX0[4], sX1[4];
    __shared__ uint32_t sFxh[4];          // half2(fx,fx)

    int tid = threadIdx.x;
    int bd = blockIdx.x & 7;            // 8 gd tiles of 16
    int bw = (blockIdx.x >> 3) & 7;     // 8 gw tiles of 16
    int bh = blockIdx.x >> 6;           // 32 gh tiles of 4

    int gh0 = bh << 2, gw0 = bw << 4, gd0 = bd << 4;

    const float s = 31.0f / 127.0f;
    int by0 = (int)floorf((float)gw0 * s);
    int bz0 = (int)floorf((float)gd0 * s);

    // ---- axis LUTs (36 threads) ----
    if (tid < 36) {
        if (tid < 16) {                 // z axis
            float v = fminf(fmaxf((float)(gd0 + tid) * s, 0.0f), 31.0f);
            int i0 = (int)floorf(v);
            int i1 = min(i0 + 1, 31);
            sOffZ[tid] = (i0 - bz0) * ZS;
            sDZ[tid]   = (i1 - i0) * ZS;
            sFz[tid]   = v - (float)i0;
        } else if (tid < 32) {          // y axis
            int l = tid - 16;
            float v = fminf(fmaxf((float)(gw0 + l) * s, 0.0f), 31.0f);
            int i0 = (int)floorf(v);
            int i1 = min(i0 + 1, 31);
            sOffY[l] = (i0 - by0) * YS;
            sDY[l]   = (i1 - i0) * YS;
            sFy[l]   = v - (float)i0;
        } else {                        // x rows
            int xr = tid - 32;
            float v = fminf(fmaxf((float)(gh0 + xr) * s, 0.0f), 31.0f);
            int i0 = (int)floorf(v);
            sX0[xr] = i0;
            sX1[xr] = min(i0 + 1, 31);
            float fx = v - (float)i0;
            __half2 h2 = __half2half2(__float2half_rn(fx));
            sFxh[xr] = *reinterpret_cast<uint32_t*>(&h2);
        }
    }
    __syncthreads();

    // ---- fill: 2304 entries = 9 x 256, x-lerp in fp16 ----
#pragma unroll
    for (int it = 0; it < 9; it++) {
        int e    = tid + (it << 8);
        int t    = e & 15;
        int cell = e >> 4;              // xr*36 + cy*6 + cz
        int cz   = cell % CZ;
        int cxy  = cell / CZ;
        int cy   = cxy % CY;
        int xr   = cxy / CY;
        int y = min(by0 + cy, 31);
        int z = min(bz0 + cz, 31);
        int base = (y * 32 + z) * 16 + t;
        uint4 e0 = g_bgP[sX0[xr] * (32 * 32 * 16) + base];
        uint4 e1 = g_bgP[sX1[xr] * (32 * 32 * 16) + base];
        uint32_t fxu = sFxh[xr];
        __half2 fx2 = *reinterpret_cast<__half2*>(&fxu);
        uint4 r;
        {
            __half2 a = *reinterpret_cast<__half2*>(&e0.x);
            __half2 b = *reinterpret_cast<__half2*>(&e1.x);
            __half2 m = __hfma2(fx2, __hsub2(b, a), a);
            r.x = *reinterpret_cast<uint32_t*>(&m);
        }
        {
            __half2 a = *reinterpret_cast<__half2*>(&e0.y);
            __half2 b = *reinterpret_cast<__half2*>(&e1.y);
            __half2 m = __hfma2(fx2, __hsub2(b, a), a);
            r.y = *reinterpret_cast<uint32_t*>(&m);
        }
        {
            __half2 a = *reinterpret_cast<__half2*>(&e0.z);
            __half2 b = *reinterpret_cast<__half2*>(&e1.z);
            __half2 m = __hfma2(fx2, __hsub2(b, a), a);
            r.z = *reinterpret_cast<uint32_t*>(&m);
        }
        {
            __half2 a = *reinterpret_cast<__half2*>(&e0.w);
            __half2 b = *reinterpret_cast<__half2*>(&e1.w);
            __half2 m = __hfma2(fx2, __hsub2(b, a), a);
            r.w = *reinterpret_cast<uint32_t*>(&m);
        }
        sgrid[e] = r;   // slot layout == fill order
    }
    __syncthreads();

    // ---- gather: 4 voxels/thread = all 4 gh rows of one (gw,gd) column ----
    int ld = tid & 15;
    int lw = tid >> 4;                // 0..15

    int offZ = sOffZ[ld], dZ = sDZ[ld]; float fz = sFz[ld];
    int offY = sOffY[lw], dY = sDY[lw]; float fy = sFy[lw];
    float wz0 = 1.0f - fz, wy0 = 1.0f - fy;
    float w00 = wy0 * wz0, w01 = wy0 * fz, w10 = fy * wz0, w11 = fy * fz;

    int idx_base = ((gw0 + lw) << 7) | (gd0 + ld);
    int byz = offY + offZ;
    int c1o = dZ, c2o = dY, c3o = dY + dZ;

    // prefetch gm for all 4 voxels (stride 16384, coalesced per row)
    float gv[4];
#pragma unroll
    for (int xr = 0; xr < 4; xr++)
        gv[xr] = __ldg(&gm[((gh0 + xr) << 14) | idx_base]);

#pragma unroll
    for (int xr = 0; xr < 4; xr++) {
        float t = fminf(fmaxf(gv[xr] * 15.0f, 0.0f), 15.0f);
        int t0 = (int)floorf(t);
        float ft = t - (float)t0;
        __half2 fth2 = __half2half2(__float2half_rn(ft));

        int b = xr * XS + byz + t0;

        float ax = 0.0f, ay = 0.0f, az = 0.0f, aw = 0.0f;
        const int   cofs[4] = { b, b + c1o, b + c2o, b + c3o };
        const float wgts[4] = { w00, w01, w10, w11 };
#pragma unroll
        for (int k = 0; k < 4; k++) {
            uint4 e = sgrid[cofs[k]];
            __half2 v0lo = *reinterpret_cast<__half2*>(&e.x);
            __half2 v0hi = *reinterpret_cast<__half2*>(&e.y);
            __half2 dlo  = *reinterpret_cast<__half2*>(&e.z);
            __half2 dhi  = *reinterpret_cast<__half2*>(&e.w);
            __half2 rlo = __hfma2(fth2, dlo, v0lo);
            __half2 rhi = __hfma2(fth2, dhi, v0hi);
            float2 flo = __half22float2(rlo);
            float2 fhi = __half22float2(rhi);
            float w = wgts[k];
            ax += w * flo.x;
            ay += w * flo.y;
            az += w * fhi.x;
            aw += w * fhi.y;
        }

        int idx = ((gh0 + xr) << 14) | idx_base;
        out[idx]            = ax;
        out[idx + NVOX]     = ay;
        out[idx + 2 * NVOX] = az;
        out[idx + 3 * NVOX] = aw;
    }
}

extern "C" void kernel_launch(void* const* d_in, const int* in_sizes, int n_in,
                              void* d_out, int out_size) {
    const float* bg = (const float*)d_in[0];
    const float* gm = (const float*)d_in[1];
    float* out = (float*)d_out;

    (void)in_sizes; (void)n_in; (void)out_size;

    bgT_pair_kernel<<<(BG_SPATIAL + 255) / 256, 256>>>(bg);
    bgrid_slice_kernel<<<2048, 256>>>(gm, out);
}

// round 12
// speedup vs baseline: 1.2290x; 1.1703x over previous
#include <cuda_runtime.h>
#include <cuda_fp16.h>
#include <stdint.h>

// bg: (1, 4, 32, 32, 32, 16) float32  -> d_in[0]
// gm: (1, 1, 128, 128, 128) float32   -> d_in[1]
// out: (1, 4, 128, 128, 128) float32

#define UP 16
#define G  128
#define NVOX (G * G * G)                 // 2,097,152
#define BG_SPATIAL (32 * 32 * 32 * 16)   // 524,288

// Plain fp16 channel-last grid: entry (x,y,z,t) = 8B {4 x fp16}. 4.2 MB.
__device__ uint2 g_bgH[BG_SPATIAL];

// ---------------------------------------------------------------------------
// Kernel 1: transpose (c,x,y,z,t) -> channel-last fp16x4.
// ---------------------------------------------------------------------------
__global__ void bgT_half_kernel(const float* __restrict__ bg) {
    int idx = blockIdx.x * blockDim.x + threadIdx.x;
    if (idx >= BG_SPATIAL) return;
    float a = __ldg(&bg[0 * BG_SPATIAL + idx]);
    float b = __ldg(&bg[1 * BG_SPATIAL + idx]);
    float c = __ldg(&bg[2 * BG_SPATIAL + idx]);
    float d = __ldg(&bg[3 * BG_SPATIAL + idx]);
    __half2 lo = __floats2half2_rn(a, b);
    __half2 hi = __floats2half2_rn(c, d);
    uint2 e;
    e.x = *reinterpret_cast<uint32_t*>(&lo);
    e.y = *reinterpret_cast<uint32_t*>(&hi);
    g_bgH[idx] = e;
}

// ---------------------------------------------------------------------------
// Kernel 2: slice with x-prelerped 8B smem entries.
// Tile = 4(gh) x 16(gw) x 16(gd) = 1024 voxels, 256 threads, 4 vox/thread
// (thread owns all 4 gh rows of one (gw,gd) column).
// smem: [xr(4)][cy(6)][cz(6)][t(17)] 8B fp16x4 entries (slot 16 = zero pad,
// only read when ft==0). Gather corner = 2 x LDS.64 (t0, t0+1), accumulated
// into fp32 A (t0 plane) and C (t1 plane); final r = A + ft*(C-A).
// ---------------------------------------------------------------------------
#define CY 6
#define CZ 6
#define ZS 17                    // slots per t-row (16 + zero pad)
#define YS (CZ * ZS)             // 102
#define XS (CY * YS)             // 612
#define NENT (4 * XS)            // 2448 entries = 19584 B
#define NFILL (4 * CY * CZ * 16) // 2304 real entries

__global__ __launch_bounds__(256)
void bgrid_slice_kernel(const float* __restrict__ gm, float* __restrict__ out) {
    __shared__ uint2    sgrid[NENT];      // 19584 B
    __shared__ int      sOffY[16], sDY[16];
    __shared__ int      sOffZ[16], sDZ[16];
    __shared__ float    sFy[16], sFz[16];
    __shared__ int      sX0[4], sX1[4];
    __shared__ uint32_t sFxh[4];          // half2(fx,fx)

    int tid = threadIdx.x;
    int bd = blockIdx.x & 7;            // 8 gd tiles of 16
    int bw = (blockIdx.x >> 3) & 7;     // 8 gw tiles of 16
    int bh = blockIdx.x >> 6;           // 32 gh tiles of 4

    int gh0 = bh << 2, gw0 = bw << 4, gd0 = bd << 4;

    const float s = 31.0f / 127.0f;
    int by0 = (int)floorf((float)gw0 * s);
    int bz0 = (int)floorf((float)gd0 * s);

    // ---- axis LUTs (36 threads) + zero pad slots (144 threads) ----
    if (tid < 36) {
        if (tid < 16) {                 // z axis
            float v = fminf(fmaxf((float)(gd0 + tid) * s, 0.0f), 31.0f);
            int i0 = (int)floorf(v);
            int i1 = min(i0 + 1, 31);
            sOffZ[tid] = (i0 - bz0) * ZS;
            sDZ[tid]   = (i1 - i0) * ZS;
            sFz[tid]   = v - (float)i0;
        } else if (tid < 32) {          // y axis
            int l = tid - 16;
            float v = fminf(fmaxf((float)(gw0 + l) * s, 0.0f), 31.0f);
            int i0 = (int)floorf(v);
            int i1 = min(i0 + 1, 31);
            sOffY[l] = (i0 - by0) * YS;
            sDY[l]   = (i1 - i0) * YS;
            sFy[l]   = v - (float)i0;
        } else {                        // x rows
            int xr = tid - 32;
            float v = fminf(fmaxf((float)(gh0 + xr) * s, 0.0f), 31.0f);
            int i0 = (int)floorf(v);
            sX0[xr] = i0;
            sX1[xr] = min(i0 + 1, 31);
            float fx = v - (float)i0;
            __half2 h2 = __half2half2(__float2half_rn(fx));
            sFxh[xr] = *reinterpret_cast<uint32_t*>(&h2);
        }
    }
    if (tid < 144) {                    // pad slot 16 of each cell row
        uint2 z; z.x = 0u; z.y = 0u;
        sgrid[tid * ZS + 16] = z;
    }
    __syncthreads();

    // ---- fill: 2304 entries = 9 x 256, x-lerp in fp16 ----
#pragma unroll
    for (int it = 0; it < 9; it++) {
        int e    = tid + (it << 8);
        int t    = e & 15;
        int cell = e >> 4;              // xr*36 + cy*6 + cz
        int cz   = cell % CZ;
        int cxy  = cell / CZ;
        int cy   = cxy % CY;
        int xr   = cxy / CY;
        int y = min(by0 + cy, 31);
        int z = min(bz0 + cz, 31);
        int base = (y * 32 + z) * 16 + t;
        uint2 e0 = g_bgH[sX0[xr] * (32 * 32 * 16) + base];
        uint2 e1 = g_bgH[sX1[xr] * (32 * 32 * 16) + base];
        uint32_t fxu = sFxh[xr];
        __half2 fx2 = *reinterpret_cast<__half2*>(&fxu);
        uint2 r;
        {
            __half2 a = *reinterpret_cast<__half2*>(&e0.x);
            __half2 b = *reinterpret_cast<__half2*>(&e1.x);
            __half2 m = __hfma2(fx2, __hsub2(b, a), a);
            r.x = *reinterpret_cast<uint32_t*>(&m);
        }
        {
            __half2 a = *reinterpret_cast<__half2*>(&e0.y);
            __half2 b = *reinterpret_cast<__half2*>(&e1.y);
            __half2 m = __hfma2(fx2, __hsub2(b, a), a);
            r.y = *reinterpret_cast<uint32_t*>(&m);
        }
        sgrid[cell * ZS + t] = r;
    }
    __syncthreads();

    // ---- gather: 4 voxels/thread = all 4 gh rows of one (gw,gd) column ----
    int ld = tid & 15;
    int lw = tid >> 4;                // 0..15

    int offZ = sOffZ[ld], dZ = sDZ[ld]; float fz = sFz[ld];
    int offY = sOffY[lw], dY = sDY[lw]; float fy = sFy[lw];
    float wz0 = 1.0f - fz, wy0 = 1.0f - fy;
    float w00 = wy0 * wz0, w01 = wy0 * fz, w10 = fy * wz0, w11 = fy * fz;

    int idx_base = ((gw0 + lw) << 7) | (gd0 + ld);
    int byz = offY + offZ;
    int c1o = dZ, c2o = dY, c3o = dY + dZ;

    // prefetch gm for all 4 voxels
    float gv[4];
#pragma unroll
    for (int xr = 0; xr < 4; xr++)
        gv[xr] = __ldg(&gm[((gh0 + xr) << 14) | idx_base]);

#pragma unroll
    for (int xr = 0; xr < 4; xr++) {
        float t = fminf(fmaxf(gv[xr] * 15.0f, 0.0f), 15.0f);
        int t0 = (int)floorf(t);
        float ft = t - (float)t0;

        int b = xr * XS + byz + t0;
        const int   cofs[4] = { b, b + c1o, b + c2o, b + c3o };
        const float wgts[4] = { w00, w01, w10, w11 };

        // A = sum w * m[t0],  C = sum w * m[t0+1]; r = A + ft*(C-A)
        float A0 = 0.f, A1 = 0.f, A2 = 0.f, A3 = 0.f;
        float C0 = 0.f, C1 = 0.f, C2 = 0.f, C3 = 0.f;
#pragma unroll
        for (int k = 0; k < 4; k++) {
            uint2 m0 = sgrid[cofs[k]];
            uint2 m1 = sgrid[cofs[k] + 1];
            float2 a_lo = __half22float2(*reinterpret_cast<__half2*>(&m0.x));
            float2 a_hi = __half22float2(*reinterpret_cast<__half2*>(&m0.y));
            float2 c_lo = __half22float2(*reinterpret_cast<__half2*>(&m1.x));
            float2 c_hi = __half22float2(*reinterpret_cast<__half2*>(&m1.y));
            float w = wgts[k];
            A0 += w * a_lo.x;  A1 += w * a_lo.y;
            A2 += w * a_hi.x;  A3 += w * a_hi.y;
            C0 += w * c_lo.x;  C1 += w * c_lo.y;
            C2 += w * c_hi.x;  C3 += w * c_hi.y;
        }

        float r0 = A0 + ft * (C0 - A0);
        float r1 = A1 + ft * (C1 - A1);
        float r2 = A2 + ft * (C2 - A2);
        float r3 = A3 + ft * (C3 - A3);

        int idx = ((gh0 + xr) << 14) | idx_base;
        out[idx]            = r0;
        out[idx + NVOX]     = r1;
        out[idx + 2 * NVOX] = r2;
        out[idx + 3 * NVOX] = r3;
    }
}

extern "C" void kernel_launch(void* const* d_in, const int* in_sizes, int n_in,
                              void* d_out, int out_size) {
    const float* bg = (const float*)d_in[0];
    const float* gm = (const float*)d_in[1];
    float* out = (float*)d_out;

    (void)in_sizes; (void)n_in; (void)out_size;

    bgT_half_kernel<<<(BG_SPATIAL + 255) / 256, 256>>>(bg);
    bgrid_slice_kernel<<<2048, 256>>>(gm, out);
}

// round 13
// speedup vs baseline: 1.2305x; 1.0012x over previous
#include <cuda_runtime.h>
#include <cuda_fp16.h>
#include <stdint.h>

// bg: (1, 4, 32, 32, 32, 16) float32  -> d_in[0]
// gm: (1, 1, 128, 128, 128) float32   -> d_in[1]
// out: (1, 4, 128, 128, 128) float32

#define UP 16
#define G  128
#define NVOX (G * G * G)                 // 2,097,152
#define BG_SPATIAL (32 * 32 * 32 * 16)   // 524,288

// Plain fp16 channel-last grid: entry (x,y,z,t) = 8B {4 x fp16}. 4.2 MB.
__device__ uint2 g_bgH[BG_SPATIAL];

// ---------------------------------------------------------------------------
// Kernel 1: transpose (c,x,y,z,t) -> channel-last fp16x4.
// ---------------------------------------------------------------------------
__global__ void bgT_half_kernel(const float* __restrict__ bg) {
    int idx = blockIdx.x * blockDim.x + threadIdx.x;
    if (idx >= BG_SPATIAL) return;
    float a = __ldg(&bg[0 * BG_SPATIAL + idx]);
    float b = __ldg(&bg[1 * BG_SPATIAL + idx]);
    float c = __ldg(&bg[2 * BG_SPATIAL + idx]);
    float d = __ldg(&bg[3 * BG_SPATIAL + idx]);
    __half2 lo = __floats2half2_rn(a, b);
    __half2 hi = __floats2half2_rn(c, d);
    uint2 e;
    e.x = *reinterpret_cast<uint32_t*>(&lo);
    e.y = *reinterpret_cast<uint32_t*>(&hi);
    g_bgH[idx] = e;
}

// ---------------------------------------------------------------------------
// Kernel 2: slice, x-prelerped 8B smem entries, fp16 A/C accumulation.
// Tile = 4(gh) x 8(gw) x 32(gd) = 1024 voxels, 256 threads, 4 vox/thread:
// thread owns 4 CONSECUTIVE gd of one (gh,gw) row -> float4 gm load and
// one STG.128 per channel (fully coalesced warp stores).
// smem: rows [xr(4)][cy(4)][cz(10)] x 18 slots of 8B (t 0..15 + 2 zero-pad;
// ZS=18 even so fill can use STS.128 on t-pairs).
// Gather corner = 2 x LDS.64 (t0, t0+1) + 4 HFMA2 into half2 A/C planes;
// final r = A + ft*(C-A) in fp32.
// ---------------------------------------------------------------------------
#define CY 4
#define CZ 10
#define ZS 18                    // slots per row (16 t + 2 pad), even
#define YS (CZ * ZS)             // 180
#define XS (CY * YS)             // 720
#define NROW (4 * CY * CZ)       // 160 rows
#define NSLOT (NROW * ZS)        // 2880 slots = 23040 B

__global__ __launch_bounds__(256)
void bgrid_slice_kernel(const float* __restrict__ gm, float* __restrict__ out) {
    __shared__ uint2    sgrid[NSLOT];     // 23040 B
    __shared__ int      sOffZ[32], sDZ[32];
    __shared__ float    sFz[32];
    __shared__ int      sOffY[8], sDY[8];
    __shared__ float    sFy[8];
    __shared__ int      sX0[4], sX1[4];
    __shared__ uint32_t sFxh[4];          // half2(fx,fx)

    int tid = threadIdx.x;
    int bd = blockIdx.x & 3;            // 4 gd tiles of 32
    int bw = (blockIdx.x >> 2) & 15;    // 16 gw tiles of 8
    int bh = blockIdx.x >> 6;           // 32 gh tiles of 4

    int gh0 = bh << 2, gw0 = bw << 3, gd0 = bd << 5;

    const float s = 31.0f / 127.0f;
    int by0 = (int)floorf((float)gw0 * s);
    int bz0 = (int)floorf((float)gd0 * s);

    // ---- axis LUTs (44 threads) ----
    if (tid < 44) {
        if (tid < 32) {                 // z axis (32 gd)
            float v = fminf(fmaxf((float)(gd0 + tid) * s, 0.0f), 31.0f);
            int i0 = (int)floorf(v);
            int i1 = min(i0 + 1, 31);
            sOffZ[tid] = (i0 - bz0) * ZS;
            sDZ[tid]   = (i1 - i0) * ZS;
            sFz[tid]   = v - (float)i0;
        } else if (tid < 40) {          // y axis (8 gw)
            int l = tid - 32;
            float v = fminf(fmaxf((float)(gw0 + l) * s, 0.0f), 31.0f);
            int i0 = (int)floorf(v);
            int i1 = min(i0 + 1, 31);
            sOffY[l] = (i0 - by0) * YS;
            sDY[l]   = (i1 - i0) * YS;
            sFy[l]   = v - (float)i0;
        } else {                        // x rows (4 gh)
            int xr = tid - 40;
            float v = fminf(fmaxf((float)(gh0 + xr) * s, 0.0f), 31.0f);
            int i0 = (int)floorf(v);
            sX0[xr] = i0;
            sX1[xr] = min(i0 + 1, 31);
            float fx = v - (float)i0;
            __half2 h2 = __half2half2(__float2half_rn(fx));
            sFxh[xr] = *reinterpret_cast<uint32_t*>(&h2);
        }
    }
    // ---- zero pad slots 16,17 of each row (320 stores) ----
    {
        uint2 z; z.x = 0u; z.y = 0u;
        int u = tid;
        if (u < 320) sgrid[(u >> 1) * ZS + 16 + (u & 1)] = z;
        u = tid + 256;
        if (u < 320) sgrid[(u >> 1) * ZS + 16 + (u & 1)] = z;
    }
    __syncthreads();

    // ---- fill: 160 rows x 8 t-pairs = 1280 units = 5 x 256, vectorized ----
    const uint4* __restrict__ bgH4 = reinterpret_cast<const uint4*>(g_bgH);
#pragma unroll
    for (int it = 0; it < 5; it++) {
        int u    = tid + (it << 8);
        int tp   = u & 7;               // t pair: t = 2*tp
        int row  = u >> 3;              // (xr*CY + cy)*CZ + cz
        int cz   = row % CZ;
        int cxy  = row / CZ;
        int cy   = cxy & 3;
        int xr   = cxy >> 2;
        int y = min(by0 + cy, 31);
        int z = min(bz0 + cz, 31);
        int base = (y * 32 + z) * 8 + tp;       // uint4 units
        uint4 e0 = bgH4[sX0[xr] * (32 * 32 * 8) + base];
        uint4 e1 = bgH4[sX1[xr] * (32 * 32 * 8) + base];
        uint32_t fxu = sFxh[xr];
        __half2 fx2 = *reinterpret_cast<__half2*>(&fxu);
        uint4 r;
        {
            __half2 a = *reinterpret_cast<__half2*>(&e0.x);
            __half2 b = *reinterpret_cast<__half2*>(&e1.x);
            __half2 m = __hfma2(fx2, __hsub2(b, a), a);
            r.x = *reinterpret_cast<uint32_t*>(&m);
        }
        {
            __half2 a = *reinterpret_cast<__half2*>(&e0.y);
            __half2 b = *reinterpret_cast<__half2*>(&e1.y);
            __half2 m = __hfma2(fx2, __hsub2(b, a), a);
            r.y = *reinterpret_cast<uint32_t*>(&m);
        }
        {
            __half2 a = *reinterpret_cast<__half2*>(&e0.z);
            __half2 b = *reinterpret_cast<__half2*>(&e1.z);
            __half2 m = __hfma2(fx2, __hsub2(b, a), a);
            r.z = *reinterpret_cast<uint32_t*>(&m);
        }
        {
            __half2 a = *reinterpret_cast<__half2*>(&e0.w);
            __half2 b = *reinterpret_cast<__half2*>(&e1.w);
            __half2 m = __hfma2(fx2, __hsub2(b, a), a);
            r.w = *reinterpret_cast<uint32_t*>(&m);
        }
        // STS.128 at slot row*18 + 2*tp (even -> 16B aligned)
        *reinterpret_cast<uint4*>(&sgrid[row * ZS + (tp << 1)]) = r;
    }
    __syncthreads();

    // ---- gather: thread = (gdq 0..7, lw 0..7, xr 0..3), 4 consecutive gd ----
    int gdq = tid & 7;
    int lw  = (tid >> 3) & 7;
    int xr  = tid >> 6;

    int offY = sOffY[lw], dY = sDY[lw]; float fy = sFy[lw];
    float wy0 = 1.0f - fy;

    int gdb = gdq << 2;                    // gd base within tile
    int idx0 = ((gh0 + xr) << 14) | ((gw0 + lw) << 7) | (gd0 + gdb);

    // gm: one float4 covers the 4 voxels
    float4 g4 = __ldg(reinterpret_cast<const float4*>(gm + idx0));
    float gv[4] = { g4.x, g4.y, g4.z, g4.w };

    int bxy = xr * XS + offY;

    float r0[4], r1[4], r2[4], r3[4];

#pragma unroll
    for (int j = 0; j < 4; j++) {
        int ldz = gdb + j;
        int offZ = sOffZ[ldz], dZ = sDZ[ldz]; float fz = sFz[ldz];
        float wz0 = 1.0f - fz;

        float t = fminf(fmaxf(gv[j] * 15.0f, 0.0f), 15.0f);
        int t0 = (int)floorf(t);
        float ft = t - (float)t0;

        int b = bxy + offZ + t0;
        const int cofs[4] = { b, b + dZ, b + dY, b + dY + dZ };
        float wf[4] = { wy0 * wz0, wy0 * fz, fy * wz0, fy * fz };

        __half2 Alo = __float2half2_rn(0.0f), Ahi = Alo, Clo = Alo, Chi = Alo;
#pragma unroll
        for (int k = 0; k < 4; k++) {
            __half2 w2 = __half2half2(__float2half_rn(wf[k]));
            uint2 m0 = sgrid[cofs[k]];
            uint2 m1 = sgrid[cofs[k] + 1];
            Alo = __hfma2(w2, *reinterpret_cast<__half2*>(&m0.x), Alo);
            Ahi = __hfma2(w2, *reinterpret_cast<__half2*>(&m0.y), Ahi);
            Clo = __hfma2(w2, *reinterpret_cast<__half2*>(&m1.x), Clo);
            Chi = __hfma2(w2, *reinterpret_cast<__half2*>(&m1.y), Chi);
        }

        float2 alo = __half22float2(Alo);
        float2 ahi = __half22float2(Ahi);
        float2 clo = __half22float2(Clo);
        float2 chi = __half22float2(Chi);

        r0[j] = alo.x + ft * (clo.x - alo.x);
        r1[j] = alo.y + ft * (clo.y - alo.y);
        r2[j] = ahi.x + ft * (chi.x - ahi.x);
        r3[j] = ahi.y + ft * (chi.y - ahi.y);
    }

    // coalesced STG.128 per channel
    float4* o0 = reinterpret_cast<float4*>(out + idx0);
    float4* o1 = reinterpret_cast<float4*>(out + idx0 + NVOX);
    float4* o2 = reinterpret_cast<float4*>(out + idx0 + 2 * NVOX);
    float4* o3 = reinterpret_cast<float4*>(out + idx0 + 3 * NVOX);
    *o0 = make_float4(r0[0], r0[1], r0[2], r0[3]);
    *o1 = make_float4(r1[0], r1[1], r1[2], r1[3]);
    *o2 = make_float4(r2[0], r2[1], r2[2], r2[3]);
    *o3 = make_float4(r3[0], r3[1], r3[2], r3[3]);
}

extern "C" void kernel_launch(void* const* d_in, const int* in_sizes, int n_in,
                              void* d_out, int out_size) {
    const float* bg = (const float*)d_in[0];
    const float* gm = (const float*)d_in[1];
    float* out = (float*)d_out;

    (void)in_sizes; (void)n_in; (void)out_size;

    bgT_half_kernel<<<(BG_SPATIAL + 255) / 256, 256>>>(bg);
    bgrid_slice_kernel<<<2048, 256>>>(gm, out);
}

// round 15
// speedup vs baseline: 1.3346x; 1.0846x over previous
#include <cuda_runtime.h>
#include <cuda_fp16.h>
#include <stdint.h>

// bg: (1, 4, 32, 32, 32, 16) float32  -> d_in[0]
// gm: (1, 1, 128, 128, 128) float32   -> d_in[1]
// out: (1, 4, 128, 128, 128) float32

#define G  128
#define NVOX (G * G * G)                 // 2,097,152
#define BG_SPATIAL (32 * 32 * 32 * 16)   // 524,288

// Plain fp16 channel-last grid: entry (x,y,z,t) = 8B {4 x fp16}. 4.2 MB.
__device__ uint2 g_bgH[BG_SPATIAL];

// ---------------------------------------------------------------------------
// Kernel 1: transpose (c,x,y,z,t) -> channel-last fp16x4.
// ---------------------------------------------------------------------------
__global__ void bgT_half_kernel(const float* __restrict__ bg) {
    int idx = blockIdx.x * blockDim.x + threadIdx.x;
    if (idx >= BG_SPATIAL) return;
    float a = __ldg(&bg[0 * BG_SPATIAL + idx]);
    float b = __ldg(&bg[1 * BG_SPATIAL + idx]);
    float c = __ldg(&bg[2 * BG_SPATIAL + idx]);
    float d = __ldg(&bg[3 * BG_SPATIAL + idx]);
    __half2 lo = __floats2half2_rn(a, b);
    __half2 hi = __floats2half2_rn(c, d);
    uint2 e;
    e.x = *reinterpret_cast<uint32_t*>(&lo);
    e.y = *reinterpret_cast<uint32_t*>(&hi);
    g_bgH[idx] = e;
}

// ---------------------------------------------------------------------------
// Kernel 2: slice. Tile = 4(gh) x 16(gw) x 32(gd) = 2048 voxels, 512 threads,
// 4 consecutive gd per thread (float4 gm load, STG.128 stores).
// Fill: the 4 gh rows share <=3 source x-planes; each fill unit (yz-cell,
// t-pair) reads those 3 planes ONCE (3 x LDG.128) and emits 4 x-lerped rows
// (4 x STS.128) -> 62% fewer fill LDGs than per-xr reads.
// smem rows: [xr(4)][cy(6)][cz(10)] x 18 slots of 8B (16 t + 2 zero pad).
// Gather corner = 2 x LDS.64 (t0, t0+1) + HFMA2 into half2 A/C planes;
// final r = A + ft*(C-A) in fp32.
// ---------------------------------------------------------------------------
#define CY 6
#define CZ 10
#define ZS 18                    // slots per row (16 t + 2 pad), even
#define YS (CZ * ZS)             // 180
#define XS (CY * YS)             // 1080
#define NROW (4 * CY * CZ)       // 240 rows
#define NSLOT (NROW * ZS)        // 4320 slots = 34560 B
#define NUNIT (CY * CZ * 8)      // 480 fill units

__global__ __launch_bounds__(512)
void bgrid_slice_kernel(const float* __restrict__ gm, float* __restrict__ out) {
    __shared__ uint2    sgrid[NSLOT];     // 34560 B
    __shared__ int      sOffZ[32], sDZ[32];
    __shared__ float    sFz[32];
    __shared__ int      sOffY[16], sDY[16];
    __shared__ float    sFy[16];
    __shared__ int      sPl0[4], sPl1[4];
    __shared__ uint32_t sFxh[4];          // half2(fx,fx)

    int tid = threadIdx.x;
    int bd = blockIdx.x & 3;            // 4 gd tiles of 32
    int bw = (blockIdx.x >> 2) & 7;     // 8 gw tiles of 16
    int bh = blockIdx.x >> 5;           // 32 gh tiles of 4

    int gh0 = bh << 2, gw0 = bw << 4, gd0 = bd << 5;

    const float s = 31.0f / 127.0f;
    int bx0 = (int)floorf((float)gh0 * s);
    int by0 = (int)floorf((float)gw0 * s);
    int bz0 = (int)floorf((float)gd0 * s);

    // ---- axis LUTs (52 threads) ----
    if (tid < 52) {
        if (tid < 32) {                 // z axis (32 gd)
            float v = fminf(fmaxf((float)(gd0 + tid) * s, 0.0f), 31.0f);
            int i0 = (int)floorf(v);
            int i1 = min(i0 + 1, 31);
            sOffZ[tid] = (i0 - bz0) * ZS;
            sDZ[tid]   = (i1 - i0) * ZS;
            sFz[tid]   = v - (float)i0;
        } else if (tid < 48) {          // y axis (16 gw)
            int l = tid - 32;
            float v = fminf(fmaxf((float)(gw0 + l) * s, 0.0f), 31.0f);
            int i0 = (int)floorf(v);
            int i1 = min(i0 + 1, 31);
            sOffY[l] = (i0 - by0) * YS;
            sDY[l]   = (i1 - i0) * YS;
            sFy[l]   = v - (float)i0;
        } else {                        // x rows (4 gh)
            int xr = tid - 48;
            float v = fminf(fmaxf((float)(gh0 + xr) * s, 0.0f), 31.0f);
            int i0 = (int)floorf(v);
            int i1 = min(i0 + 1, 31);
            sPl0[xr] = i0 - bx0;        // 0 or 1
            sPl1[xr] = i1 - bx0;        // 0, 1 or 2
            float fx = v - (float)i0;
            __half2 h2 = __half2half2(__float2half_rn(fx));
            sFxh[xr] = *reinterpret_cast<uint32_t*>(&h2);
        }
    }
    // ---- zero pad slots 16,17 of each row (480 stores) ----
    if (tid < 2 * NROW) {
        uint2 z; z.x = 0u; z.y = 0u;
        sgrid[(tid >> 1) * ZS + 16 + (tid & 1)] = z;
    }
    __syncthreads();

    // ---- fill: 480 units, one pass. 3 LDG.128 + 4 x (lerp + STS.128) ----
    const uint4* __restrict__ bgH4 = reinterpret_cast<const uint4*>(g_bgH);
    if (tid < NUNIT) {
        int tp   = tid & 7;             // t pair: t = 2*tp
        int cell = tid >> 3;            // cy*CZ + cz  (0..59)
        int cz   = cell % CZ;
        int cy   = cell / CZ;
        int y = min(by0 + cy, 31);
        int z = min(bz0 + cz, 31);
        int base = (y * 32 + z) * 8 + tp;     // uint4 units within an x-plane

        int xs0 = bx0;
        int xs1 = min(bx0 + 1, 31);
        int xs2 = min(bx0 + 2, 31);
        uint4 s0 = bgH4[xs0 * (32 * 32 * 8) + base];
        uint4 s1 = bgH4[xs1 * (32 * 32 * 8) + base];
        uint4 s2 = bgH4[xs2 * (32 * 32 * 8) + base];

#pragma unroll
        for (int xr = 0; xr < 4; xr++) {
            int pl0 = sPl0[xr];
            int pl1 = sPl1[xr];
            uint4 a = (pl0 == 0) ? s0 : s1;
            uint4 b = (pl1 == 0) ? s0 : ((pl1 == 1) ? s1 : s2);
            uint32_t fxu = sFxh[xr];
            __half2 fx2 = *reinterpret_cast<__half2*>(&fxu);
            uint4 r;
            {
                __half2 av = *reinterpret_cast<__half2*>(&a.x);
                __half2 bv = *reinterpret_cast<__half2*>(&b.x);
                __half2 m = __hfma2(fx2, __hsub2(bv, av), av);
                r.x = *reinterpret_cast<uint32_t*>(&m);
            }
            {
                __half2 av = *reinterpret_cast<__half2*>(&a.y);
                __half2 bv = *reinterpret_cast<__half2*>(&b.y);
                __half2 m = __hfma2(fx2, __hsub2(bv, av), av);
                r.y = *reinterpret_cast<uint32_t*>(&m);
            }
            {
                __half2 av = *reinterpret_cast<__half2*>(&a.z);
                __half2 bv = *reinterpret_cast<__half2*>(&b.z);
                __half2 m = __hfma2(fx2, __hsub2(bv, av), av);
                r.z = *reinterpret_cast<uint32_t*>(&m);
            }
            {
                __half2 av = *reinterpret_cast<__half2*>(&a.w);
                __half2 bv = *reinterpret_cast<__half2*>(&b.w);
                __half2 m = __hfma2(fx2, __hsub2(bv, av), av);
                r.w = *reinterpret_cast<uint32_t*>(&m);
            }
            int row = (xr * CY + cy) * CZ + cz;
            *reinterpret_cast<uint4*>(&sgrid[row * ZS + (tp << 1)]) = r;
        }
    }
    __syncthreads();

    // ---- gather: thread = (gdq 0..7, lw 0..15, xr 0..3), 4 consecutive gd ----
    int gdq = tid & 7;
    int lw  = (tid >> 3) & 15;
    int xr  = tid >> 7;

    int offY = sOffY[lw], dY = sDY[lw]; float fy = sFy[lw];
    float wy0 = 1.0f - fy;

    int gdb = gdq << 2;                    // gd base within tile
    int idx0 = ((gh0 + xr) << 14) | ((gw0 + lw) << 7) | (gd0 + gdb);

    // gm: one float4 covers the 4 voxels
    float4 g4 = __ldg(reinterpret_cast<const float4*>(gm + idx0));
    float gv[4] = { g4.x, g4.y, g4.z, g4.w };

    int bxy = xr * XS + offY;

    float r0[4], r1[4], r2[4], r3[4];

#pragma unroll
    for (int j = 0; j < 4; j++) {
        int ldz = gdb + j;
        int offZ = sOffZ[ldz], dZ = sDZ[ldz]; float fz = sFz[ldz];
        float wz0 = 1.0f - fz;

        float t = fminf(fmaxf(gv[j] * 15.0f, 0.0f), 15.0f);
        int t0 = (int)floorf(t);
        float ft = t - (float)t0;

        int b = bxy + offZ + t0;
        const int cofs[4] = { b, b + dZ, b + dY, b + dY + dZ };
        float wf[4] = { wy0 * wz0, wy0 * fz, fy * wz0, fy * fz };

        __half2 Alo = __float2half2_rn(0.0f), Ahi = Alo, Clo = Alo, Chi = Alo;
#pragma unroll
        for (int k = 0; k < 4; k++) {
            __half2 w2 = __half2half2(__float2half_rn(wf[k]));
            uint2 m0 = sgrid[cofs[k]];
            uint2 m1 = sgrid[cofs[k] + 1];
            Alo = __hfma2(w2, *reinterpret_cast<__half2*>(&m0.x), Alo);
            Ahi = __hfma2(w2, *reinterpret_cast<__half2*>(&m0.y), Ahi);
            Clo = __hfma2(w2, *reinterpret_cast<__half2*>(&m1.x), Clo);
            Chi = __hfma2(w2, *reinterpret_cast<__half2*>(&m1.y), Chi);
        }

        float2 alo = __half22float2(Alo);
        float2 ahi = __half22float2(Ahi);
        float2 clo = __half22float2(Clo);
        float2 chi = __half22float2(Chi);

        r0[j] = alo.x + ft * (clo.x - alo.x);
        r1[j] = alo.y + ft * (clo.y - alo.y);
        r2[j] = ahi.x + ft * (chi.x - ahi.x);
        r3[j] = ahi.y + ft * (chi.y - ahi.y);
    }

    // coalesced STG.128 per channel
    float4* o0 = reinterpret_cast<float4*>(out + idx0);
    float4* o1 = reinterpret_cast<float4*>(out + idx0 + NVOX);
    float4* o2 = reinterpret_cast<float4*>(out + idx0 + 2 * NVOX);
    float4* o3 = reinterpret_cast<float4*>(out + idx0 + 3 * NVOX);
    *o0 = make_float4(r0[0], r0[1], r0[2], r0[3]);
    *o1 = make_float4(r1[0], r1[1], r1[2], r1[3]);
    *o2 = make_float4(r2[0], r2[1], r2[2], r2[3]);
    *o3 = make_float4(r3[0], r3[1], r3[2], r3[3]);
}

extern "C" void kernel_launch(void* const* d_in, const int* in_sizes, int n_in,
                              void* d_out, int out_size) {
    const float* bg = (const float*)d_in[0];
    const float* gm = (const float*)d_in[1];
    float* out = (float*)d_out;

    (void)in_sizes; (void)n_in; (void)out_size;

    bgT_half_kernel<<<(BG_SPATIAL + 255) / 256, 256>>>(bg);
    bgrid_slice_kernel<<<1024, 512>>>(gm, out);
}